// round 13
// baseline (speedup 1.0000x reference)
#include <cuda_runtime.h>
#include <math.h>
#include <float.h>

#define B_TOT 8192
#define F 32
#define P 512
#define H 256
#define M 16          // samples per CTA
#define T 256         // threads per CTA (== H)

typedef unsigned long long u64;

// ---- packed f32x2 helpers (FFMA2 only reachable via PTX on sm_103a) ----
static __device__ __forceinline__ u64 pack2(float a, float b) {
    u64 r;
    asm("mov.b64 %0, {%1, %2};" : "=l"(r)
        : "r"(__float_as_uint(a)), "r"(__float_as_uint(b)));
    return r;
}
static __device__ __forceinline__ void unpack2(u64 v, float &a, float &b) {
    unsigned lo, hi;
    asm("mov.b64 {%0, %1}, %2;" : "=r"(lo), "=r"(hi) : "l"(v));
    a = __uint_as_float(lo);
    b = __uint_as_float(hi);
}
static __device__ __forceinline__ void fma2(u64 &d, u64 a, u64 b) {
    asm("fma.rn.f32x2 %0, %1, %2, %0;" : "+l"(d) : "l"(a), "l"(b));
}

__global__ __launch_bounds__(T)
void PhysChemLinearMix_49323404427796_kernel(
    const float* __restrict__ phys,     // [B,F,P]
    const float* __restrict__ ratios,   // [B,F]
    const int*   __restrict__ lengths,  // [B]
    const float* __restrict__ gamma,    // [P]
    const float* __restrict__ beta,     // [P]
    const float* __restrict__ W1,       // [H,P]
    const float* __restrict__ b1,       // [H]
    const float* __restrict__ W2,       // [1,H]
    const float* __restrict__ b2,       // [1]
    float*       __restrict__ out)      // [B,1]
{
    __shared__ float s_w[M][F];                       // normalized mix weights
    __shared__ __align__(16) float s_xn[M][P];        // mix, then layernormed mix
    __shared__ float s_r0[M][8];                      // reduction scratch
    __shared__ float s_mu[M];
    __shared__ float s_rstd[M];

    const int tid  = threadIdx.x;
    const int warp = tid >> 5;
    const int lane = tid & 31;
    const int b0   = blockIdx.x * M;

    // ---------------- Phase 0: ragged weight normalization ----------------
    // warp w handles samples m = 2w, 2w+1 (lane == fragment index, F==32)
    #pragma unroll
    for (int s = 0; s < 2; s++) {
        const int m = warp * 2 + s;
        const int b = b0 + m;
        float r = ratios[b * F + lane];
        const int len = lengths[b];
        if (lane >= len) r = 0.f;
        float sum = r;
        #pragma unroll
        for (int off = 16; off > 0; off >>= 1)
            sum += __shfl_xor_sync(0xffffffffu, sum, off);
        s_w[m][lane] = r / (sum + 1e-8f);
    }
    __syncthreads();

    // ---------------- Phase 1: weighted mix (the 512 MiB stream) ----------
    // Half-block owns one sample per iteration; thread owns column-quad q.
    // 32 independent LDG.128 per sample, explicitly double-buffered (8 in
    // flight) so DRAM latency is covered by MLP, not ptxas luck.
    const int half = tid >> 7;     // 0/1: which sample of the pair
    const int q    = tid & 127;    // float4 index within P/4 = 128

    #pragma unroll
    for (int it = 0; it < M / 2; it++) {
        const int m = 2 * it + half;
        const float4* base = reinterpret_cast<const float4*>(
            phys + (size_t)(b0 + m) * (F * P)) + q;   // row stride = P/4 = 128

        u64 acc01 = 0ull, acc23 = 0ull;
        float4 a0, a1, a2, a3, v0, v1, v2, v3;

        // prologue: rows 0..3 in flight
        a0 = __ldg(base + 0 * 128); a1 = __ldg(base + 1 * 128);
        a2 = __ldg(base + 2 * 128); a3 = __ldg(base + 3 * 128);

        #pragma unroll
        for (int c = 0; c < 8; c += 2) {
            const int fA = c * 4;
            const int fB = (c + 1) * 4;
            // issue next 4 loads (rows fB..fB+3) before consuming A
            v0 = __ldg(base + (fB + 0) * 128);
            v1 = __ldg(base + (fB + 1) * 128);
            v2 = __ldg(base + (fB + 2) * 128);
            v3 = __ldg(base + (fB + 3) * 128);
            {
                const u64 w0 = pack2(s_w[m][fA + 0], s_w[m][fA + 0]);
                fma2(acc01, w0, pack2(a0.x, a0.y)); fma2(acc23, w0, pack2(a0.z, a0.w));
                const u64 w1 = pack2(s_w[m][fA + 1], s_w[m][fA + 1]);
                fma2(acc01, w1, pack2(a1.x, a1.y)); fma2(acc23, w1, pack2(a1.z, a1.w));
                const u64 w2 = pack2(s_w[m][fA + 2], s_w[m][fA + 2]);
                fma2(acc01, w2, pack2(a2.x, a2.y)); fma2(acc23, w2, pack2(a2.z, a2.w));
                const u64 w3 = pack2(s_w[m][fA + 3], s_w[m][fA + 3]);
                fma2(acc01, w3, pack2(a3.x, a3.y)); fma2(acc23, w3, pack2(a3.z, a3.w));
            }
            if (c + 2 < 8) {
                const int fN = (c + 2) * 4;   // prefetch rows for next A slot
                a0 = __ldg(base + (fN + 0) * 128);
                a1 = __ldg(base + (fN + 1) * 128);
                a2 = __ldg(base + (fN + 2) * 128);
                a3 = __ldg(base + (fN + 3) * 128);
            }
            {
                const u64 w0 = pack2(s_w[m][fB + 0], s_w[m][fB + 0]);
                fma2(acc01, w0, pack2(v0.x, v0.y)); fma2(acc23, w0, pack2(v0.z, v0.w));
                const u64 w1 = pack2(s_w[m][fB + 1], s_w[m][fB + 1]);
                fma2(acc01, w1, pack2(v1.x, v1.y)); fma2(acc23, w1, pack2(v1.z, v1.w));
                const u64 w2 = pack2(s_w[m][fB + 2], s_w[m][fB + 2]);
                fma2(acc01, w2, pack2(v2.x, v2.y)); fma2(acc23, w2, pack2(v2.z, v2.w));
                const u64 w3 = pack2(s_w[m][fB + 3], s_w[m][fB + 3]);
                fma2(acc01, w3, pack2(v3.x, v3.y)); fma2(acc23, w3, pack2(v3.z, v3.w));
            }
        }

        float4 r;
        unpack2(acc01, r.x, r.y);
        unpack2(acc23, r.z, r.w);
        *reinterpret_cast<float4*>(&s_xn[m][4 * q]) = r;   // raw mix to SMEM
    }
    __syncthreads();

    // ---------------- Phase 2: LayerNorm statistics (from SMEM) -----------
    // warp w -> samples 2w, 2w+1; lane reads consecutive float4 (no conflicts)
    #pragma unroll
    for (int s = 0; s < 2; s++) {
        const int m = warp * 2 + s;
        float sum = 0.f, sq = 0.f;
        #pragma unroll
        for (int k = 0; k < 4; k++) {
            const float4 v = *reinterpret_cast<const float4*>(
                &s_xn[m][(k * 32 + lane) * 4]);
            sum += v.x + v.y + v.z + v.w;
            sq  += v.x * v.x + v.y * v.y + v.z * v.z + v.w * v.w;
        }
        #pragma unroll
        for (int off = 16; off > 0; off >>= 1) {
            sum += __shfl_xor_sync(0xffffffffu, sum, off);
            sq  += __shfl_xor_sync(0xffffffffu, sq,  off);
        }
        if (lane == 0) {
            const float mu = sum * (1.0f / (float)P);
            float var = sq * (1.0f / (float)P) - mu * mu;
            var = fmaxf(var, 0.f);
            s_mu[m]   = mu;
            s_rstd[m] = rsqrtf(var + 1e-5f);
        }
    }
    __syncthreads();

    // ---------------- Phase 3: normalize in place -------------------------
    {
        const float4 gv = reinterpret_cast<const float4*>(gamma)[q];
        const float4 bv = reinterpret_cast<const float4*>(beta)[q];
        #pragma unroll
        for (int it = 0; it < M / 2; it++) {
            const int m = 2 * it + half;
            const float mu = s_mu[m], rs = s_rstd[m];
            float4 v = *reinterpret_cast<const float4*>(&s_xn[m][4 * q]);
            v.x = (v.x - mu) * rs * gv.x + bv.x;
            v.y = (v.y - mu) * rs * gv.y + bv.y;
            v.z = (v.z - mu) * rs * gv.z + bv.z;
            v.w = (v.w - mu) * rs * gv.w + bv.w;
            *reinterpret_cast<float4*>(&s_xn[m][4 * q]) = v;
        }
    }
    __syncthreads();

    // ---------------- Phase 4: Linear(P,H) + ReLU, f32x2 packed -----------
    // Thread t == output neuron j. W1 row streamed as float4 (L1/L2-resident
    // after wave 1). xn broadcast from SMEM via uniform LDS.128.
    const int j = tid;
    const float4* wrow = reinterpret_cast<const float4*>(W1 + j * P);
    u64 acc[M];
    #pragma unroll
    for (int m = 0; m < M; m++) acc[m] = 0ull;

    #pragma unroll 2
    for (int k = 0; k < P / 4; k++) {
        const float4 wv = __ldg(wrow + k);
        const u64 w01 = pack2(wv.x, wv.y);
        const u64 w23 = pack2(wv.z, wv.w);
        #pragma unroll
        for (int m = 0; m < M; m++) {
            const float4 xv = *reinterpret_cast<const float4*>(&s_xn[m][4 * k]);
            fma2(acc[m], w01, pack2(xv.x, xv.y));
            fma2(acc[m], w23, pack2(xv.z, xv.w));
        }
    }

    const float b1j = b1[j];
    const float w2j = W2[j];
    float c[M];
    #pragma unroll
    for (int m = 0; m < M; m++) {
        float lo, hi;
        unpack2(acc[m], lo, hi);
        float h = lo + hi + b1j;
        h = fmaxf(h, 0.f);      // ReLU
        c[m] = h * w2j;         // fold W2 into the reduction
    }

    // ---------------- Phase 5: Linear(H,1) via block reduction ------------
    #pragma unroll
    for (int m = 0; m < M; m++) {
        float v = c[m];
        #pragma unroll
        for (int off = 16; off > 0; off >>= 1)
            v += __shfl_xor_sync(0xffffffffu, v, off);
        if (lane == 0) s_r0[m][warp] = v;
    }
    __syncthreads();
    if (tid < M) {
        float S = 0.f;
        #pragma unroll
        for (int w = 0; w < 8; w++) S += s_r0[tid][w];
        float y = S + b2[0];
        // jnp.nan_to_num semantics
        if (isnan(y))      y = 0.f;
        else if (isinf(y)) y = (y > 0.f) ? FLT_MAX : -FLT_MAX;
        out[b0 + tid] = y;
    }
}

extern "C" void kernel_launch(void* const* d_in, const int* in_sizes, int n_in,
                              void* d_out, int out_size) {
    const float* phys    = (const float*)d_in[0];
    const float* ratios  = (const float*)d_in[1];
    const int*   lengths = (const int*)  d_in[2];
    const float* gamma   = (const float*)d_in[3];
    const float* beta    = (const float*)d_in[4];
    const float* W1      = (const float*)d_in[5];
    const float* b1      = (const float*)d_in[6];
    const float* W2      = (const float*)d_in[7];
    const float* b2      = (const float*)d_in[8];
    float* out = (float*)d_out;

    PhysChemLinearMix_49323404427796_kernel<<<B_TOT / M, T>>>(
        phys, ratios, lengths, gamma, beta, W1, b1, W2, b2, out);
}

// round 14
// speedup vs baseline: 1.2494x; 1.2494x over previous
#include <cuda_runtime.h>
#include <math.h>
#include <float.h>

#define B_TOT 8192
#define F 32
#define P 512
#define H 256
#define M 16            // samples per CTA
#define T 256           // threads per CTA (== H)
#define KC 32           // W1 k-chunk (floats) staged in SMEM
#define WSTRIDE 36      // padded SMEM row stride (floats): conflict-free LDS.128

typedef unsigned long long u64;

// ---- packed f32x2 helpers ------------------------------------------------
static __device__ __forceinline__ u64 pack2(float a, float b) {
    u64 r;
    asm("mov.b64 %0, {%1, %2};" : "=l"(r)
        : "r"(__float_as_uint(a)), "r"(__float_as_uint(b)));
    return r;
}
static __device__ __forceinline__ void unpack2(u64 v, float &a, float &b) {
    unsigned lo, hi;
    asm("mov.b64 {%0, %1}, %2;" : "=r"(lo), "=r"(hi) : "l"(v));
    a = __uint_as_float(lo);
    b = __uint_as_float(hi);
}
static __device__ __forceinline__ void fma2(u64 &d, u64 a, u64 b) {
    asm("fma.rn.f32x2 %0, %1, %2, %0;" : "+l"(d) : "l"(a), "l"(b));
}
// double <-> packed pair is a free bit-cast (same register pair)
static __device__ __forceinline__ u64 dbits(double d) {
    return __double_as_longlong(d);
}

// Dynamic SMEM layout (74368 B total):
//   [0,     4096)  double s_wp[M][F]     packed (w,w) mix weights
//   [4096, 36864)  float  s_xn[M][P]     mix -> layernormed mix
//   [36864,73728)  float  s_w1[H][36]    staged W1 chunk (padded rows)
//   [73728,74240)  float  s_r0[M][8]
//   [74240,74304)  float  s_mu[M]
//   [74304,74368)  float  s_rstd[M]
#define SMEM_BYTES 74368

__global__ __launch_bounds__(T, 3)
void PhysChemLinearMix_49323404427796_kernel(
    const float* __restrict__ phys,     // [B,F,P]
    const float* __restrict__ ratios,   // [B,F]
    const int*   __restrict__ lengths,  // [B]
    const float* __restrict__ gamma,    // [P]
    const float* __restrict__ beta,     // [P]
    const float* __restrict__ W1,       // [H,P]
    const float* __restrict__ b1,       // [H]
    const float* __restrict__ W2,       // [1,H]
    const float* __restrict__ b2,       // [1]
    float*       __restrict__ out)      // [B,1]
{
    extern __shared__ __align__(16) char smem[];
    double (*s_wp)[F] = reinterpret_cast<double(*)[F]>(smem);
    float  (*s_xn)[P] = reinterpret_cast<float(*)[P]>(smem + 4096);
    float*  s_w1      = reinterpret_cast<float*>(smem + 36864);
    float  (*s_r0)[8] = reinterpret_cast<float(*)[8]>(smem + 73728);
    float*  s_mu      = reinterpret_cast<float*>(smem + 74240);
    float*  s_rstd    = reinterpret_cast<float*>(smem + 74304);

    const int tid  = threadIdx.x;
    const int warp = tid >> 5;
    const int lane = tid & 31;
    const int b0   = blockIdx.x * M;

    // ---------------- Phase 0: ragged weight normalization ----------------
    #pragma unroll
    for (int s = 0; s < 2; s++) {
        const int m = warp * 2 + s;
        const int b = b0 + m;
        float r = ratios[b * F + lane];
        const int len = lengths[b];
        if (lane >= len) r = 0.f;
        float sum = r;
        #pragma unroll
        for (int off = 16; off > 0; off >>= 1)
            sum += __shfl_xor_sync(0xffffffffu, sum, off);
        const float wn = r / (sum + 1e-8f);
        s_wp[m][lane] = __longlong_as_double(pack2(wn, wn));   // pre-packed
    }
    __syncthreads();

    // ---------------- Phase 1: weighted mix (512 MiB stream) --------------
    // Half-block owns one sample; thread owns float4-quad q. double2 loads
    // deliver packed pairs directly (zero MOV). Double-buffered depth 4.
    const int half = tid >> 7;
    const int q    = tid & 127;

    #pragma unroll
    for (int it = 0; it < M / 2; it++) {
        const int m = 2 * it + half;
        const double2* base = reinterpret_cast<const double2*>(
            phys + (size_t)(b0 + m) * (F * P)) + q;   // row stride = 128

        u64 a01 = 0ull, a23 = 0ull;
        double2 buf[2][4];
        #pragma unroll
        for (int r = 0; r < 4; r++) buf[0][r] = __ldg(base + r * 128);

        #pragma unroll
        for (int g = 0; g < 8; g++) {
            const int cur = g & 1;
            if (g < 7) {
                #pragma unroll
                for (int r = 0; r < 4; r++)
                    buf[cur ^ 1][r] = __ldg(base + ((g + 1) * 4 + r) * 128);
            }
            #pragma unroll
            for (int r = 0; r < 4; r++) {
                const u64 w = dbits(s_wp[m][g * 4 + r]);
                fma2(a01, w, dbits(buf[cur][r].x));
                fma2(a23, w, dbits(buf[cur][r].y));
            }
        }
        float x0, x1, x2, x3;
        unpack2(a01, x0, x1);
        unpack2(a23, x2, x3);
        *reinterpret_cast<float4*>(&s_xn[m][4 * q]) = make_float4(x0, x1, x2, x3);
    }
    __syncthreads();

    // ---------------- Phase 2: LayerNorm statistics -----------------------
    #pragma unroll
    for (int s = 0; s < 2; s++) {
        const int m = warp * 2 + s;
        float sum = 0.f, sq = 0.f;
        #pragma unroll
        for (int k = 0; k < 4; k++) {
            const float4 v = *reinterpret_cast<const float4*>(
                &s_xn[m][(k * 32 + lane) * 4]);
            sum += v.x + v.y + v.z + v.w;
            sq  += v.x * v.x + v.y * v.y + v.z * v.z + v.w * v.w;
        }
        #pragma unroll
        for (int off = 16; off > 0; off >>= 1) {
            sum += __shfl_xor_sync(0xffffffffu, sum, off);
            sq  += __shfl_xor_sync(0xffffffffu, sq,  off);
        }
        if (lane == 0) {
            const float mu = sum * (1.0f / (float)P);
            float var = sq * (1.0f / (float)P) - mu * mu;
            var = fmaxf(var, 0.f);
            s_mu[m]   = mu;
            s_rstd[m] = rsqrtf(var + 1e-5f);
        }
    }
    __syncthreads();

    // ---------------- Phase 3: normalize in place -------------------------
    {
        const float4 gv = reinterpret_cast<const float4*>(gamma)[q];
        const float4 bv = reinterpret_cast<const float4*>(beta)[q];
        #pragma unroll
        for (int it = 0; it < M / 2; it++) {
            const int m = 2 * it + half;
            const float mu = s_mu[m], rs = s_rstd[m];
            float4 v = *reinterpret_cast<const float4*>(&s_xn[m][4 * q]);
            v.x = (v.x - mu) * rs * gv.x + bv.x;
            v.y = (v.y - mu) * rs * gv.y + bv.y;
            v.z = (v.z - mu) * rs * gv.z + bv.z;
            v.w = (v.w - mu) * rs * gv.w + bv.w;
            *reinterpret_cast<float4*>(&s_xn[m][4 * q]) = v;
        }
    }
    __syncthreads();

    // ---------------- Phase 4: Linear(P,H) + ReLU -------------------------
    // W1 staged chunk-by-chunk into SMEM (coalesced LDG, padded rows so the
    // per-neuron LDS.128 is conflict-free). xn broadcast via uniform LDS.128.
    // All operands live as packed pairs -> pure FFMA2 inner loop.
    const int j = tid;
    u64 acc[M];
    #pragma unroll
    for (int m = 0; m < M; m++) acc[m] = 0ull;

    for (int c = 0; c < P / KC; c++) {          // 16 chunks
        // cooperative stage: W1[:, c*KC .. c*KC+31] -> s_w1[r][qk*4..]
        #pragma unroll
        for (int i = 0; i < 8; i++) {
            const int idx = i * 256 + tid;
            const int r   = idx >> 3;           // row 0..255
            const int qk  = idx & 7;            // quad 0..7 within chunk
            const float4 v = __ldg(
                reinterpret_cast<const float4*>(W1 + r * P + c * KC) + qk);
            *reinterpret_cast<float4*>(s_w1 + r * WSTRIDE + qk * 4) = v;
        }
        __syncthreads();

        #pragma unroll
        for (int kq = 0; kq < 8; kq++) {
            const double2 wv = *reinterpret_cast<const double2*>(
                s_w1 + j * WSTRIDE + kq * 4);
            const u64 w01 = dbits(wv.x);
            const u64 w23 = dbits(wv.y);
            #pragma unroll
            for (int m = 0; m < M; m++) {
                const double2 xv = *reinterpret_cast<const double2*>(
                    &s_xn[m][c * KC + kq * 4]);
                fma2(acc[m], w01, dbits(xv.x));
                fma2(acc[m], w23, dbits(xv.y));
            }
        }
        __syncthreads();
    }

    const float b1j = b1[j];
    const float w2j = W2[j];
    float cres[M];
    #pragma unroll
    for (int m = 0; m < M; m++) {
        float lo, hi;
        unpack2(acc[m], lo, hi);
        float h = lo + hi + b1j;
        h = fmaxf(h, 0.f);          // ReLU
        cres[m] = h * w2j;          // fold W2 into the reduction
    }

    // ---------------- Phase 5: Linear(H,1) via block reduction ------------
    #pragma unroll
    for (int m = 0; m < M; m++) {
        float v = cres[m];
        #pragma unroll
        for (int off = 16; off > 0; off >>= 1)
            v += __shfl_xor_sync(0xffffffffu, v, off);
        if (lane == 0) s_r0[m][warp] = v;
    }
    __syncthreads();
    if (tid < M) {
        float S = 0.f;
        #pragma unroll
        for (int w = 0; w < 8; w++) S += s_r0[tid][w];
        float y = S + b2[0];
        if (isnan(y))      y = 0.f;                          // nan_to_num
        else if (isinf(y)) y = (y > 0.f) ? FLT_MAX : -FLT_MAX;
        out[b0 + tid] = y;
    }
}

extern "C" void kernel_launch(void* const* d_in, const int* in_sizes, int n_in,
                              void* d_out, int out_size) {
    const float* phys    = (const float*)d_in[0];
    const float* ratios  = (const float*)d_in[1];
    const int*   lengths = (const int*)  d_in[2];
    const float* gamma   = (const float*)d_in[3];
    const float* beta    = (const float*)d_in[4];
    const float* W1      = (const float*)d_in[5];
    const float* b1      = (const float*)d_in[6];
    const float* W2      = (const float*)d_in[7];
    const float* b2      = (const float*)d_in[8];
    float* out = (float*)d_out;

    cudaFuncSetAttribute(PhysChemLinearMix_49323404427796_kernel,
                         cudaFuncAttributeMaxDynamicSharedMemorySize,
                         SMEM_BYTES);
    PhysChemLinearMix_49323404427796_kernel<<<B_TOT / M, T, SMEM_BYTES>>>(
        phys, ratios, lengths, gamma, beta, W1, b1, W2, b2, out);
}

// round 15
// speedup vs baseline: 1.2527x; 1.0027x over previous
#include <cuda_runtime.h>
#include <math.h>
#include <float.h>

#define B_TOT 8192
#define F 32
#define P 512
#define H 256
#define M 16            // samples per CTA
#define T 256           // threads per CTA (== H)
#define KC 32           // W1 k-chunk (floats) staged in SMEM
#define WSTRIDE 36      // padded SMEM row stride (floats): conflict-free LDS.128

typedef unsigned long long u64;

// ---- packed f32x2 helpers ------------------------------------------------
static __device__ __forceinline__ u64 pack2(float a, float b) {
    u64 r;
    asm("mov.b64 %0, {%1, %2};" : "=l"(r)
        : "r"(__float_as_uint(a)), "r"(__float_as_uint(b)));
    return r;
}
static __device__ __forceinline__ void unpack2(u64 v, float &a, float &b) {
    unsigned lo, hi;
    asm("mov.b64 {%0, %1}, %2;" : "=r"(lo), "=r"(hi) : "l"(v));
    a = __uint_as_float(lo);
    b = __uint_as_float(hi);
}
static __device__ __forceinline__ void fma2(u64 &d, u64 a, u64 b) {
    asm("fma.rn.f32x2 %0, %1, %2, %0;" : "+l"(d) : "l"(a), "l"(b));
}
// double <-> packed pair is a free bit-cast (same register pair)
static __device__ __forceinline__ u64 dbits(double d) {
    return __double_as_longlong(d);
}

// Dynamic SMEM layout (74368 B total):
//   [0,     4096)  double s_wp[M][F]     packed (w,w) mix weights
//   [4096, 36864)  float  s_xn[M][P]     mix -> layernormed mix
//   [36864,73728)  float  s_w1[H][36]    staged W1 chunk (padded rows)
//   [73728,74240)  float  s_r0[M][8]
//   [74240,74304)  float  s_mu[M]
//   [74304,74368)  float  s_rstd[M]
#define SMEM_BYTES 74368

__global__ __launch_bounds__(T, 3)
void PhysChemLinearMix_49323404427796_kernel(
    const float* __restrict__ phys,     // [B,F,P]
    const float* __restrict__ ratios,   // [B,F]
    const int*   __restrict__ lengths,  // [B]
    const float* __restrict__ gamma,    // [P]
    const float* __restrict__ beta,     // [P]
    const float* __restrict__ W1,       // [H,P]
    const float* __restrict__ b1,       // [H]
    const float* __restrict__ W2,       // [1,H]
    const float* __restrict__ b2,       // [1]
    float*       __restrict__ out)      // [B,1]
{
    extern __shared__ __align__(16) char smem[];
    double (*s_wp)[F] = reinterpret_cast<double(*)[F]>(smem);
    float  (*s_xn)[P] = reinterpret_cast<float(*)[P]>(smem + 4096);
    float*  s_w1      = reinterpret_cast<float*>(smem + 36864);
    float  (*s_r0)[8] = reinterpret_cast<float(*)[8]>(smem + 73728);
    float*  s_mu      = reinterpret_cast<float*>(smem + 74240);
    float*  s_rstd    = reinterpret_cast<float*>(smem + 74304);

    const int tid  = threadIdx.x;
    const int warp = tid >> 5;
    const int lane = tid & 31;
    const int b0   = blockIdx.x * M;

    // ---------------- Phase 0: ragged weight normalization ----------------
    #pragma unroll
    for (int s = 0; s < 2; s++) {
        const int m = warp * 2 + s;
        const int b = b0 + m;
        float r = ratios[b * F + lane];
        const int len = lengths[b];
        if (lane >= len) r = 0.f;
        float sum = r;
        #pragma unroll
        for (int off = 16; off > 0; off >>= 1)
            sum += __shfl_xor_sync(0xffffffffu, sum, off);
        const float wn = r / (sum + 1e-8f);
        s_wp[m][lane] = __longlong_as_double(pack2(wn, wn));   // pre-packed
    }
    __syncthreads();

    // ---------------- Phase 1: weighted mix (512 MiB stream) --------------
    // Half-block owns one sample; thread owns float4-quad q. double2 loads
    // deliver packed pairs directly (zero MOV). Double-buffered depth 4.
    const int half = tid >> 7;
    const int q    = tid & 127;

    #pragma unroll
    for (int it = 0; it < M / 2; it++) {
        const int m = 2 * it + half;
        const double2* base = reinterpret_cast<const double2*>(
            phys + (size_t)(b0 + m) * (F * P)) + q;   // row stride = 128

        u64 a01 = 0ull, a23 = 0ull;
        double2 buf[2][4];
        #pragma unroll
        for (int r = 0; r < 4; r++) buf[0][r] = __ldg(base + r * 128);

        #pragma unroll
        for (int g = 0; g < 8; g++) {
            const int cur = g & 1;
            if (g < 7) {
                #pragma unroll
                for (int r = 0; r < 4; r++)
                    buf[cur ^ 1][r] = __ldg(base + ((g + 1) * 4 + r) * 128);
            }
            #pragma unroll
            for (int r = 0; r < 4; r++) {
                const u64 w = dbits(s_wp[m][g * 4 + r]);
                fma2(a01, w, dbits(buf[cur][r].x));
                fma2(a23, w, dbits(buf[cur][r].y));
            }
        }
        float x0, x1, x2, x3;
        unpack2(a01, x0, x1);
        unpack2(a23, x2, x3);
        *reinterpret_cast<float4*>(&s_xn[m][4 * q]) = make_float4(x0, x1, x2, x3);
    }
    __syncthreads();

    // ---------------- Phase 2: LayerNorm statistics -----------------------
    #pragma unroll
    for (int s = 0; s < 2; s++) {
        const int m = warp * 2 + s;
        float sum = 0.f, sq = 0.f;
        #pragma unroll
        for (int k = 0; k < 4; k++) {
            const float4 v = *reinterpret_cast<const float4*>(
                &s_xn[m][(k * 32 + lane) * 4]);
            sum += v.x + v.y + v.z + v.w;
            sq  += v.x * v.x + v.y * v.y + v.z * v.z + v.w * v.w;
        }
        #pragma unroll
        for (int off = 16; off > 0; off >>= 1) {
            sum += __shfl_xor_sync(0xffffffffu, sum, off);
            sq  += __shfl_xor_sync(0xffffffffu, sq,  off);
        }
        if (lane == 0) {
            const float mu = sum * (1.0f / (float)P);
            float var = sq * (1.0f / (float)P) - mu * mu;
            var = fmaxf(var, 0.f);
            s_mu[m]   = mu;
            s_rstd[m] = rsqrtf(var + 1e-5f);
        }
    }
    __syncthreads();

    // ---------------- Phase 3: normalize in place -------------------------
    {
        const float4 gv = reinterpret_cast<const float4*>(gamma)[q];
        const float4 bv = reinterpret_cast<const float4*>(beta)[q];
        #pragma unroll
        for (int it = 0; it < M / 2; it++) {
            const int m = 2 * it + half;
            const float mu = s_mu[m], rs = s_rstd[m];
            float4 v = *reinterpret_cast<const float4*>(&s_xn[m][4 * q]);
            v.x = (v.x - mu) * rs * gv.x + bv.x;
            v.y = (v.y - mu) * rs * gv.y + bv.y;
            v.z = (v.z - mu) * rs * gv.z + bv.z;
            v.w = (v.w - mu) * rs * gv.w + bv.w;
            *reinterpret_cast<float4*>(&s_xn[m][4 * q]) = v;
        }
    }
    __syncthreads();

    // ---------------- Phase 4: Linear(P,H) + ReLU -------------------------
    // W1 staged chunk-by-chunk into SMEM (coalesced LDG, padded rows so the
    // per-neuron LDS.128 is conflict-free). xn broadcast via uniform LDS.128.
    // All operands live as packed pairs -> pure FFMA2 inner loop.
    const int j = tid;
    u64 acc[M];
    #pragma unroll
    for (int m = 0; m < M; m++) acc[m] = 0ull;

    for (int c = 0; c < P / KC; c++) {          // 16 chunks
        // cooperative stage: W1[:, c*KC .. c*KC+31] -> s_w1[r][qk*4..]
        #pragma unroll
        for (int i = 0; i < 8; i++) {
            const int idx = i * 256 + tid;
            const int r   = idx >> 3;           // row 0..255
            const int qk  = idx & 7;            // quad 0..7 within chunk
            const float4 v = __ldg(
                reinterpret_cast<const float4*>(W1 + r * P + c * KC) + qk);
            *reinterpret_cast<float4*>(s_w1 + r * WSTRIDE + qk * 4) = v;
        }
        __syncthreads();

        #pragma unroll
        for (int kq = 0; kq < 8; kq++) {
            const double2 wv = *reinterpret_cast<const double2*>(
                s_w1 + j * WSTRIDE + kq * 4);
            const u64 w01 = dbits(wv.x);
            const u64 w23 = dbits(wv.y);
            #pragma unroll
            for (int m = 0; m < M; m++) {
                const double2 xv = *reinterpret_cast<const double2*>(
                    &s_xn[m][c * KC + kq * 4]);
                fma2(acc[m], w01, dbits(xv.x));
                fma2(acc[m], w23, dbits(xv.y));
            }
        }
        __syncthreads();
    }

    const float b1j = b1[j];
    const float w2j = W2[j];
    float cres[M];
    #pragma unroll
    for (int m = 0; m < M; m++) {
        float lo, hi;
        unpack2(acc[m], lo, hi);
        float h = lo + hi + b1j;
        h = fmaxf(h, 0.f);          // ReLU
        cres[m] = h * w2j;          // fold W2 into the reduction
    }

    // ---------------- Phase 5: Linear(H,1) via block reduction ------------
    #pragma unroll
    for (int m = 0; m < M; m++) {
        float v = cres[m];
        #pragma unroll
        for (int off = 16; off > 0; off >>= 1)
            v += __shfl_xor_sync(0xffffffffu, v, off);
        if (lane == 0) s_r0[m][warp] = v;
    }
    __syncthreads();
    if (tid < M) {
        float S = 0.f;
        #pragma unroll
        for (int w = 0; w < 8; w++) S += s_r0[tid][w];
        float y = S + b2[0];
        if (isnan(y))      y = 0.f;                          // nan_to_num
        else if (isinf(y)) y = (y > 0.f) ? FLT_MAX : -FLT_MAX;
        out[b0 + tid] = y;
    }
}

extern "C" void kernel_launch(void* const* d_in, const int* in_sizes, int n_in,
                              void* d_out, int out_size) {
    const float* phys    = (const float*)d_in[0];
    const float* ratios  = (const float*)d_in[1];
    const int*   lengths = (const int*)  d_in[2];
    const float* gamma   = (const float*)d_in[3];
    const float* beta    = (const float*)d_in[4];
    const float* W1      = (const float*)d_in[5];
    const float* b1      = (const float*)d_in[6];
    const float* W2      = (const float*)d_in[7];
    const float* b2      = (const float*)d_in[8];
    float* out = (float*)d_out;

    cudaFuncSetAttribute(PhysChemLinearMix_49323404427796_kernel,
                         cudaFuncAttributeMaxDynamicSharedMemorySize,
                         SMEM_BYTES);
    PhysChemLinearMix_49323404427796_kernel<<<B_TOT / M, T, SMEM_BYTES>>>(
        phys, ratios, lengths, gamma, beta, W1, b1, W2, b2, out);
}

// round 16
// speedup vs baseline: 1.3654x; 1.0900x over previous
#include <cuda_runtime.h>
#include <math.h>
#include <float.h>

#define B_TOT 8192
#define F 32
#define P 512
#define H 256
#define M 16            // samples per CTA
#define T 256           // threads per CTA
#define KC 32           // W1 k-chunk (floats) staged in SMEM
#define WSTRIDE 36      // padded SMEM row stride (floats): conflict-free LDS.128

typedef unsigned long long u64;

// ---- packed f32x2 helpers ------------------------------------------------
static __device__ __forceinline__ u64 pack2(float a, float b) {
    u64 r;
    asm("mov.b64 %0, {%1, %2};" : "=l"(r)
        : "r"(__float_as_uint(a)), "r"(__float_as_uint(b)));
    return r;
}
static __device__ __forceinline__ void unpack2(u64 v, float &a, float &b) {
    unsigned lo, hi;
    asm("mov.b64 {%0, %1}, %2;" : "=r"(lo), "=r"(hi) : "l"(v));
    a = __uint_as_float(lo);
    b = __uint_as_float(hi);
}
static __device__ __forceinline__ void fma2(u64 &d, u64 a, u64 b) {
    asm("fma.rn.f32x2 %0, %1, %2, %0;" : "+l"(d) : "l"(a), "l"(b));
}
static __device__ __forceinline__ u64 dbits(double d) {
    return __double_as_longlong(d);
}

// Dynamic SMEM layout (74368 B total):
//   [0,     4096)  double s_wp[M][F]     packed (w,w) mix weights
//   [4096, 36864)  float  s_xn[M][P]     mix -> layernormed mix
//   [36864,73728)  float  s_w1[H][36]    staged W1 chunk (padded rows)
//   [73728,74240)  float  s_r0[M][8]
//   [74240,74304)  float  s_mu[M]
//   [74304,74368)  float  s_rstd[M]
#define SMEM_BYTES 74368

__global__ __launch_bounds__(T, 3)
void PhysChemLinearMix_49323404427796_kernel(
    const float* __restrict__ phys,     // [B,F,P]
    const float* __restrict__ ratios,   // [B,F]
    const int*   __restrict__ lengths,  // [B]
    const float* __restrict__ gamma,    // [P]
    const float* __restrict__ beta,     // [P]
    const float* __restrict__ W1,       // [H,P]
    const float* __restrict__ b1,       // [H]
    const float* __restrict__ W2,       // [1,H]
    const float* __restrict__ b2,       // [1]
    float*       __restrict__ out)      // [B,1]
{
    extern __shared__ __align__(16) char smem[];
    double (*s_wp)[F] = reinterpret_cast<double(*)[F]>(smem);
    float  (*s_xn)[P] = reinterpret_cast<float(*)[P]>(smem + 4096);
    float*  s_w1      = reinterpret_cast<float*>(smem + 36864);
    float  (*s_r0)[8] = reinterpret_cast<float(*)[8]>(smem + 73728);
    float*  s_mu      = reinterpret_cast<float*>(smem + 74240);
    float*  s_rstd    = reinterpret_cast<float*>(smem + 74304);

    const int tid  = threadIdx.x;
    const int warp = tid >> 5;
    const int lane = tid & 31;
    const int b0   = blockIdx.x * M;

    // ---------------- Phase 0: ragged weight normalization ----------------
    #pragma unroll
    for (int s = 0; s < 2; s++) {
        const int m = warp * 2 + s;
        const int b = b0 + m;
        float r = ratios[b * F + lane];
        const int len = lengths[b];
        if (lane >= len) r = 0.f;
        float sum = r;
        #pragma unroll
        for (int off = 16; off > 0; off >>= 1)
            sum += __shfl_xor_sync(0xffffffffu, sum, off);
        const float wn = r / (sum + 1e-8f);
        s_wp[m][lane] = __longlong_as_double(pack2(wn, wn));   // pre-packed
    }
    __syncthreads();

    // ---------------- Phase 1: weighted mix (512 MiB stream) --------------
    const int half = tid >> 7;     // 0/1
    const int q    = tid & 127;    // float4-quad within P/4 = 128

    #pragma unroll
    for (int it = 0; it < M / 2; it++) {
        const int m = 2 * it + half;
        const double2* base = reinterpret_cast<const double2*>(
            phys + (size_t)(b0 + m) * (F * P)) + q;   // row stride = 128

        u64 a01 = 0ull, a23 = 0ull;
        double2 buf[2][4];
        #pragma unroll
        for (int r = 0; r < 4; r++) buf[0][r] = __ldg(base + r * 128);

        #pragma unroll
        for (int g = 0; g < 8; g++) {
            const int cur = g & 1;
            if (g < 7) {
                #pragma unroll
                for (int r = 0; r < 4; r++)
                    buf[cur ^ 1][r] = __ldg(base + ((g + 1) * 4 + r) * 128);
            }
            #pragma unroll
            for (int r = 0; r < 4; r++) {
                const u64 w = dbits(s_wp[m][g * 4 + r]);
                fma2(a01, w, dbits(buf[cur][r].x));
                fma2(a23, w, dbits(buf[cur][r].y));
            }
        }
        float x0, x1, x2, x3;
        unpack2(a01, x0, x1);
        unpack2(a23, x2, x3);
        *reinterpret_cast<float4*>(&s_xn[m][4 * q]) = make_float4(x0, x1, x2, x3);
    }
    __syncthreads();

    // ---------------- Phase 2: LayerNorm statistics -----------------------
    #pragma unroll
    for (int s = 0; s < 2; s++) {
        const int m = warp * 2 + s;
        float sum = 0.f, sq = 0.f;
        #pragma unroll
        for (int k = 0; k < 4; k++) {
            const float4 v = *reinterpret_cast<const float4*>(
                &s_xn[m][(k * 32 + lane) * 4]);
            sum += v.x + v.y + v.z + v.w;
            sq  += v.x * v.x + v.y * v.y + v.z * v.z + v.w * v.w;
        }
        #pragma unroll
        for (int off = 16; off > 0; off >>= 1) {
            sum += __shfl_xor_sync(0xffffffffu, sum, off);
            sq  += __shfl_xor_sync(0xffffffffu, sq,  off);
        }
        if (lane == 0) {
            const float mu = sum * (1.0f / (float)P);
            float var = sq * (1.0f / (float)P) - mu * mu;
            var = fmaxf(var, 0.f);
            s_mu[m]   = mu;
            s_rstd[m] = rsqrtf(var + 1e-5f);
        }
    }
    __syncthreads();

    // ---------------- Phase 3: normalize in place -------------------------
    {
        const float4 gv = reinterpret_cast<const float4*>(gamma)[q];
        const float4 bv = reinterpret_cast<const float4*>(beta)[q];
        #pragma unroll
        for (int it = 0; it < M / 2; it++) {
            const int m = 2 * it + half;
            const float mu = s_mu[m], rs = s_rstd[m];
            float4 v = *reinterpret_cast<const float4*>(&s_xn[m][4 * q]);
            v.x = (v.x - mu) * rs * gv.x + bv.x;
            v.y = (v.y - mu) * rs * gv.y + bv.y;
            v.z = (v.z - mu) * rs * gv.z + bv.z;
            v.w = (v.w - mu) * rs * gv.w + bv.w;
            *reinterpret_cast<float4*>(&s_xn[m][4 * q]) = v;
        }
    }
    __syncthreads();

    // ---------------- Phase 4: Linear(P,H) + ReLU, register-tiled ---------
    // Thread t computes J=2 neurons {j0, j0+128} for M=8 samples (its half).
    // Per (chunk,kq): 2 w-loads + 8 x-loads feed 32 FFMA2 (5 B smem/FFMA2,
    // was ~8.5). w LDS.128 at padded stride 36 is conflict-free; x loads are
    // warp-uniform broadcasts.
    const int j0 = tid & 127;
    const int m0 = half * 8;       // this thread's sample window

    u64 accA[8], accB[8];
    #pragma unroll
    for (int m = 0; m < 8; m++) { accA[m] = 0ull; accB[m] = 0ull; }

    for (int c = 0; c < P / KC; c++) {          // 16 chunks
        // cooperative stage: W1[:, c*KC .. c*KC+31] -> s_w1
        #pragma unroll
        for (int i = 0; i < 8; i++) {
            const int idx = i * 256 + tid;
            const int r   = idx >> 3;           // row 0..255
            const int qk  = idx & 7;            // quad 0..7 within chunk
            const float4 v = __ldg(
                reinterpret_cast<const float4*>(W1 + r * P + c * KC) + qk);
            *reinterpret_cast<float4*>(s_w1 + r * WSTRIDE + qk * 4) = v;
        }
        __syncthreads();

        #pragma unroll
        for (int kq = 0; kq < 8; kq++) {
            const double2 wvA = *reinterpret_cast<const double2*>(
                s_w1 + j0 * WSTRIDE + kq * 4);
            const double2 wvB = *reinterpret_cast<const double2*>(
                s_w1 + (j0 + 128) * WSTRIDE + kq * 4);
            const u64 wA01 = dbits(wvA.x), wA23 = dbits(wvA.y);
            const u64 wB01 = dbits(wvB.x), wB23 = dbits(wvB.y);
            #pragma unroll
            for (int m = 0; m < 8; m++) {
                const double2 xv = *reinterpret_cast<const double2*>(
                    &s_xn[m0 + m][c * KC + kq * 4]);
                const u64 x01 = dbits(xv.x), x23 = dbits(xv.y);
                fma2(accA[m], wA01, x01);
                fma2(accA[m], wA23, x23);
                fma2(accB[m], wB01, x01);
                fma2(accB[m], wB23, x23);
            }
        }
        __syncthreads();
    }

    // ---------------- Phase 5: epilogue + Linear(H,1) reduction -----------
    const float b1A = b1[j0];
    const float b1B = b1[j0 + 128];
    const float w2A = W2[j0];
    const float w2B = W2[j0 + 128];

    const int wrow = warp & 3;     // 4 warps per half
    #pragma unroll
    for (int m = 0; m < 8; m++) {
        float lo, hi;
        unpack2(accA[m], lo, hi);
        float hA = fmaxf(lo + hi + b1A, 0.f);
        unpack2(accB[m], lo, hi);
        float hB = fmaxf(lo + hi + b1B, 0.f);
        float v = hA * w2A + hB * w2B;
        #pragma unroll
        for (int off = 16; off > 0; off >>= 1)
            v += __shfl_xor_sync(0xffffffffu, v, off);
        if (lane == 0) s_r0[m0 + m][wrow] = v;
    }
    __syncthreads();
    if (tid < M) {
        float S = 0.f;
        #pragma unroll
        for (int w = 0; w < 4; w++) S += s_r0[tid][w];
        float y = S + b2[0];
        if (isnan(y))      y = 0.f;                          // nan_to_num
        else if (isinf(y)) y = (y > 0.f) ? FLT_MAX : -FLT_MAX;
        out[b0 + tid] = y;
    }
}

extern "C" void kernel_launch(void* const* d_in, const int* in_sizes, int n_in,
                              void* d_out, int out_size) {
    const float* phys    = (const float*)d_in[0];
    const float* ratios  = (const float*)d_in[1];
    const int*   lengths = (const int*)  d_in[2];
    const float* gamma   = (const float*)d_in[3];
    const float* beta    = (const float*)d_in[4];
    const float* W1      = (const float*)d_in[5];
    const float* b1      = (const float*)d_in[6];
    const float* W2      = (const float*)d_in[7];
    const float* b2      = (const float*)d_in[8];
    float* out = (float*)d_out;

    cudaFuncSetAttribute(PhysChemLinearMix_49323404427796_kernel,
                         cudaFuncAttributeMaxDynamicSharedMemorySize,
                         SMEM_BYTES);
    PhysChemLinearMix_49323404427796_kernel<<<B_TOT / M, T, SMEM_BYTES>>>(
        phys, ratios, lengths, gamma, beta, W1, b1, W2, b2, out);
}